// round 9
// baseline (speedup 1.0000x reference)
#include <cuda_runtime.h>
#include <cstdint>

// Problem constants (fixed by setup_inputs)
#define BATCH 4
#define LEN   2048
#define DIM   64
#define KMAX  64

// Bloom filter: per batch, per group (lo/hi), 2^18 bits = 32 KB. k=2 hashes.
#define BLOOM_LG    18
#define BLOOM_BITS  (1u << BLOOM_LG)          // 262144
#define BLOOM_WORDS (BLOOM_BITS / 32)         // 8192
#define BLOOM_MASK  (BLOOM_BITS - 1u)

// __device__ globals = allowed scratch (no allocation APIs anywhere).
__device__ uint2    g_keys [BATCH * LEN];                 // packed key bits
__device__ uint2    g_qbits[BATCH * LEN];                 // packed query bits
__device__ unsigned g_bloom[BATCH * 2 * BLOOM_WORDS];     // 256 KB filters

// ---------------------------------------------------------------------------
// Kernel Z: zero the bloom filters. 64 blocks x 256 threads, 1 STG.128 each.
// (Must re-zero every call: kernel_launch is replayed via graph.)
// ---------------------------------------------------------------------------
__global__ void zero_bloom_kernel() {
    int i = blockIdx.x * blockDim.x + threadIdx.x;   // 16384 uint4 = 256 KB
    ((uint4*)g_bloom)[i] = make_uint4(0u, 0u, 0u, 0u);
}

// ---------------------------------------------------------------------------
// Kernel P: pack sign bits for keys AND queries (one warp per token), and
// for keys set the 4 bloom bits (2 hashes x 2 groups) via atomicOr (REDG).
// ballot returns the same word on every lane, so lanes 0..3 can each issue
// one independent atomic (MLP=4).
// ---------------------------------------------------------------------------
__global__ void pack_build_kernel(const float* __restrict__ query_up,
                                  const float* __restrict__ key_up) {
    int w    = (blockIdx.x * blockDim.x + threadIdx.x) >> 5;  // token-warp id
    int lane = threadIdx.x & 31;
    bool is_q = (w >= BATCH * LEN);
    int tok   = is_q ? (w - BATCH * LEN) : w;

    const float* p = (is_q ? query_up : key_up) + (size_t)tok * DIM;
    unsigned lo = __ballot_sync(0xFFFFFFFFu, p[lane]      > 0.0f);
    unsigned hi = __ballot_sync(0xFFFFFFFFu, p[lane + 32] > 0.0f);

    if (is_q) {
        if (lane == 0) g_qbits[tok] = make_uint2(lo, hi);
        return;
    }
    if (lane == 0) g_keys[tok] = make_uint2(lo, hi);

    int b = tok >> 11;                                   // batch
    if (lane < 4) {
        unsigned word = (lane < 2) ? lo : hi;
        int grp = lane >> 1;                             // 0 = lo, 1 = hi
        unsigned h = (lane & 1) ? ((word >> 14) & BLOOM_MASK)
                                : (word & BLOOM_MASK);
        atomicOr(&g_bloom[(b * 2 + grp) * BLOOM_WORDS + (h >> 5)],
                 1u << (h & 31));
    }
}

// ---------------------------------------------------------------------------
// Kernel F: one THREAD per query. Probe 4 bloom bits; a query is "suspect"
// iff both hashes hit in either group (includes every true match). With a
// fixed random seed the expected suspect count is ~4 of 8192.
// Fast path (ballot==0): warp blanket-writes its 32 queries' outputs with
// -1.0f -- 16 perfectly-coalesced STG.128 covering 8 KB contiguous.
// Rare path: per suspect lane, the whole warp runs the R7-proven ordered
// ballot scan over g_keys (exact "smallest indices first" semantics), pads
// with -1; non-suspect queries get predicated blanket -1s. Every output
// address is written exactly once (no write races).
// ---------------------------------------------------------------------------
__global__ void __launch_bounds__(256)
find_bloom_kernel(float* __restrict__ out) {
    int t    = blockIdx.x * blockDim.x + threadIdx.x;    // query id 0..8191
    int lane = threadIdx.x & 31;
    int b    = t >> 11;                                  // warp-uniform (2048%32==0)

    uint2 qb = g_qbits[t];                               // coalesced LDG.64

    const unsigned* blo = g_bloom + (size_t)(b * 2 + 0) * BLOOM_WORDS;
    const unsigned* bhi = g_bloom + (size_t)(b * 2 + 1) * BLOOM_WORDS;
    unsigned h0 = qb.x & BLOOM_MASK, h1 = (qb.x >> 14) & BLOOM_MASK;
    unsigned h2 = qb.y & BLOOM_MASK, h3 = (qb.y >> 14) & BLOOM_MASK;
    bool slo = ((blo[h0 >> 5] >> (h0 & 31)) & 1u) &&
               ((blo[h1 >> 5] >> (h1 & 31)) & 1u);
    bool shi = ((bhi[h2 >> 5] >> (h2 & 31)) & 1u) &&
               ((bhi[h3 >> 5] >> (h3 & 31)) & 1u);
    bool suspect = slo || shi;

    unsigned susp = __ballot_sync(0xFFFFFFFFu, suspect);

    // Warp's output region: 32 queries x 64 floats = 512 float4, contiguous.
    float4  neg   = make_float4(-1.0f, -1.0f, -1.0f, -1.0f);
    float4* wbase = (float4*)(out + (size_t)(t & ~31) * KMAX);

    if (susp == 0u) {                                    // statistically certain
        #pragma unroll
        for (int j = 0; j < 16; ++j)
            wbase[j * 32 + lane] = neg;                  // coalesced 512B stores
        return;
    }

    // ---- RARE PATH ----
    // Blanket -1 only for non-suspect queries (float4 f belongs to query f>>4).
    #pragma unroll
    for (int j = 0; j < 16; ++j) {
        int f = j * 32 + lane;
        if (!((susp >> (f >> 4)) & 1u)) wbase[f] = neg;
    }
    // Exact ordered scan for each suspect query (warp-cooperative).
    const uint2* gk = g_keys + (size_t)b * LEN;
    unsigned lt_mask = (1u << lane) - 1u;
    while (susp) {
        int s = __ffs(susp) - 1;  susp &= susp - 1u;
        unsigned sqlo = __shfl_sync(0xFFFFFFFFu, qb.x, s);
        unsigned sqhi = __shfl_sync(0xFFFFFFFFu, qb.y, s);
        float* so = out + (size_t)((t & ~31) + s) * KMAX;
        int count = 0;
        for (int c = 0; c < LEN / 32; ++c) {
            int j = c * 32 + lane;
            uint2 k = gk[j];
            bool m = (k.x == sqlo) | (k.y == sqhi);
            unsigned mask = __ballot_sync(0xFFFFFFFFu, m);
            if (mask) {
                int pos = count + __popc(mask & lt_mask);
                if (m && pos < KMAX) so[pos] = (float)j;
                count += __popc(mask);
                if (count >= KMAX) break;                // warp-uniform
            }
        }
        for (int p = count + lane; p < KMAX; p += 32)    // pad this query
            so[p] = -1.0f;
    }
}

// ---------------------------------------------------------------------------
// Launch: inputs = query_up (f32), key_up (f32), head_idx (unused).
// Three graph-capturable kernel launches, no syncs, no allocations.
// ---------------------------------------------------------------------------
extern "C" void kernel_launch(void* const* d_in, const int* in_sizes, int n_in,
                              void* d_out, int out_size) {
    const float* query_up = (const float*)d_in[0];
    const float* key_up   = (const float*)d_in[1];
    float* out = (float*)d_out;

    zero_bloom_kernel<<<64, 256>>>();                       // 256 KB
    // 16384 token-warps (8192 keys + 8192 queries), 8 warps per block
    pack_build_kernel<<<2 * BATCH * LEN / 8, 256>>>(query_up, key_up);
    // one thread per query: 8192 threads
    find_bloom_kernel<<<BATCH * LEN / 256, 256>>>(out);
}

// round 10
// speedup vs baseline: 2.4881x; 2.4881x over previous
#include <cuda_runtime.h>
#include <cstdint>

// Problem constants (fixed by setup_inputs)
#define BATCH 4
#define LEN   2048
#define DIM   64
#define KMAX  64
#define NQ    8        // queries per warp in the find kernel

// Packed key bits per token: uint2 = (lo bits d0..31, hi bits d32..63).
__device__ uint2 g_keys[BATCH * LEN];

// ---------------------------------------------------------------------------
// Kernel 1: pack key sign bits. One warp per token, two ballots.
// ---------------------------------------------------------------------------
__global__ void pack_keys_kernel(const float* __restrict__ key_up) {
    int warp = (blockIdx.x * blockDim.x + threadIdx.x) >> 5;
    int lane = threadIdx.x & 31;
    if (warp >= BATCH * LEN) return;
    const float* p = key_up + (size_t)warp * DIM;
    unsigned lo = __ballot_sync(0xFFFFFFFFu, p[lane]      > 0.0f);
    unsigned hi = __ballot_sync(0xFFFFFFFFu, p[lane + 32] > 0.0f);
    if (lane == 0) g_keys[warp] = make_uint2(lo, hi);
}

// ---------------------------------------------------------------------------
// Kernel 2: candidate scan, 8 queries per warp.
// Block = 128 threads = 4 warps = 32 queries; grid = 256 blocks (1 wave).
// Block caches its batch's 2048 packed keys (16 KB) in smem; each warp packs
// its 8 queries via ballot (fused -- no separate qbits kernel), then scans:
// per chunk ONE LDS.128 gives each lane 2 key-pairs = 64 keys/warp; 8x4
// chained equality-ORs accumulate per-query per-lane match flags. 32 chunks
// cover all 2048 keys with 8x less smem-crossbar traffic than one-query-
// per-warp. Eight end ballots detect matches (P ~ 2^-32 each); the
// statistically-certain no-match path blanket-writes -1.0f coalesced.
// Suspects fall back to the exact ordered ballot scan (R7 semantics).
// ---------------------------------------------------------------------------
__global__ void __launch_bounds__(128)
find_cands_kernel(const float* __restrict__ query_up, float* __restrict__ out) {
    __shared__ uint2 skeys[LEN];

    int b    = blockIdx.x >> 6;            // 64 blocks per batch
    int warp = threadIdx.x >> 5;
    int lane = threadIdx.x & 31;
    int q0   = blockIdx.x * 32 + warp * NQ;   // first of this warp's 8 queries

    // Cooperative key fill: 1024 uint4 / 128 threads = 8 LDG.128 each (L2)
    const uint4* gk4 = (const uint4*)(g_keys + (size_t)b * LEN);
    uint4* sk4 = (uint4*)skeys;
    #pragma unroll
    for (int i = 0; i < 8; ++i)
        sk4[i * 128 + threadIdx.x] = gk4[i * 128 + threadIdx.x];

    // Pack this warp's 8 queries (overlaps with the key-fill LDGs)
    unsigned qlo[NQ], qhi[NQ];
    const float* qp = query_up + (size_t)q0 * DIM;
    #pragma unroll
    for (int i = 0; i < NQ; ++i) {
        qlo[i] = __ballot_sync(0xFFFFFFFFu, qp[i * DIM + lane]      > 0.0f);
        qhi[i] = __ballot_sync(0xFFFFFFFFu, qp[i * DIM + 32 + lane] > 0.0f);
    }
    __syncthreads();

    // Main scan: 32 chunks x 64 keys. acc[i] != 0 iff one of this lane's
    // keys matched query i. No cross-lane ops inside the loop.
    unsigned acc[NQ];
    #pragma unroll
    for (int i = 0; i < NQ; ++i) acc[i] = 0u;

    const uint4* sq = (const uint4*)skeys;
    #pragma unroll 4
    for (int c = 0; c < LEN / 64; ++c) {
        uint4 k = sq[c * 32 + lane];        // key-pairs 2*(c*32+lane), +1
        #pragma unroll
        for (int i = 0; i < NQ; ++i)
            acc[i] |= (unsigned)((k.x == qlo[i]) | (k.y == qhi[i]) |
                                 (k.z == qlo[i]) | (k.w == qhi[i]));
    }

    // Which of the 8 queries have any match anywhere?
    unsigned susp = 0u;
    #pragma unroll
    for (int i = 0; i < NQ; ++i)
        if (__ballot_sync(0xFFFFFFFFu, acc[i] != 0u)) susp |= 1u << i;

    // Warp's output region: 8 queries x 64 floats = 2 KB = 128 float4.
    float4  neg = make_float4(-1.0f, -1.0f, -1.0f, -1.0f);
    float4* wo  = (float4*)(out + (size_t)q0 * KMAX);

    if (__builtin_expect(susp == 0u, 1)) {  // statistically certain
        #pragma unroll
        for (int j = 0; j < 4; ++j)
            wo[j * 32 + lane] = neg;        // coalesced 512B stores
        return;
    }

    // ---- RARE PATH ----
    // Blanket -1 for non-suspect queries (float4 f belongs to query f>>4).
    #pragma unroll
    for (int j = 0; j < 4; ++j) {
        int f = j * 32 + lane;
        if (!((susp >> (f >> 4)) & 1u)) wo[f] = neg;
    }
    // Exact ordered ballot scan per suspect query (warp-cooperative).
    unsigned lt_mask = (1u << lane) - 1u;
    while (susp) {
        int i = __ffs((int)susp) - 1;  susp &= susp - 1u;
        unsigned sqlo = qlo[i], sqhi = qhi[i];
        float* so = out + (size_t)(q0 + i) * KMAX;
        int count = 0;
        for (int c = 0; c < LEN / 32; ++c) {
            int j = c * 32 + lane;
            uint2 k = skeys[j];
            bool m = (k.x == sqlo) | (k.y == sqhi);
            unsigned mask = __ballot_sync(0xFFFFFFFFu, m);
            if (mask) {
                int pos = count + __popc(mask & lt_mask);
                if (m && pos < KMAX) so[pos] = (float)j;
                count += __popc(mask);
                if (count >= KMAX) break;   // warp-uniform
            }
        }
        for (int p = count + lane; p < KMAX; p += 32)
            so[p] = -1.0f;
    }
}

// ---------------------------------------------------------------------------
// Launch: inputs = query_up (f32), key_up (f32), head_idx (unused).
// Two graph-capturable launches, no syncs, no allocations.
// ---------------------------------------------------------------------------
extern "C" void kernel_launch(void* const* d_in, const int* in_sizes, int n_in,
                              void* d_out, int out_size) {
    const float* query_up = (const float*)d_in[0];
    const float* key_up   = (const float*)d_in[1];
    float* out = (float*)d_out;

    // 8192 key tokens, 8 warps per 256-thread block -> 1024 blocks
    pack_keys_kernel<<<(BATCH * LEN) / 8, 256>>>(key_up);
    // 32 queries per 128-thread block -> 256 blocks (single wave)
    find_cands_kernel<<<(BATCH * LEN) / 32, 128>>>(query_up, out);
}